// round 8
// baseline (speedup 1.0000x reference)
#include <cuda_runtime.h>
#include <cstdint>

#define B_      8
#define C_      256
#define H_      128
#define W_      128
#define HW_     (H_ * W_)
#define GROUPS_ 32
#define CPG_    8
#define EPS_    1e-5f
#define AST     68                 // attn smem row stride (floats): 272B, 16B-aligned, odd f4-stride

typedef unsigned long long u64;

// ---------------------------------------------------------------------------
// Scratch
// ---------------------------------------------------------------------------
__device__ float  g_Yq[(size_t)B_ * C_ * HW_];
__device__ float  g_Yk[(size_t)B_ * C_ * HW_];
__device__ float  g_Wt[2][C_ * C_];            // W transposed: [c][o]
__device__ float  g_psum[2][B_][GROUPS_][2];   // (sum, sumsq) accumulators
__device__ float2 g_stats[2][B_][GROUPS_];     // (mean, rstd)

// ---------------------------------------------------------------------------
// Packed fp32x2 helpers (FFMA2 — full fp32 precision, 2 MAC/instr)
// ---------------------------------------------------------------------------
#define FMA2(acc, a, b) asm("fma.rn.f32x2 %0, %1, %2, %0;" : "+l"(acc) : "l"(a), "l"(b))

__device__ __forceinline__ u64 bcast2(float f) {
    u64 d; unsigned u = __float_as_uint(f);
    asm("mov.b64 %0, {%1, %1};" : "=l"(d) : "r"(u));
    return d;
}
__device__ __forceinline__ float2 unpack2(u64 p) {
    unsigned a, b;
    asm("mov.b64 {%0, %1}, %2;" : "=r"(a), "=r"(b) : "l"(p));
    return make_float2(__uint_as_float(a), __uint_as_float(b));
}

// ---------------------------------------------------------------------------
// Kernel A: zero the GN accumulators (graph replays re-run this each launch)
// ---------------------------------------------------------------------------
__global__ void init_kernel() {
    ((float*)g_psum)[threadIdx.x] = 0.f;      // 1024 threads, 1024 floats
}

// ---------------------------------------------------------------------------
// Kernel 0: transpose W (256x256)
// ---------------------------------------------------------------------------
__global__ __launch_bounds__(256) void wtrans_kernel(
    const float* __restrict__ Wq, const float* __restrict__ Wk)
{
    __shared__ float t[32][33];
    const float* Wm = blockIdx.z ? Wk : Wq;
    float* T = g_Wt[blockIdx.z];
    const int bx = blockIdx.x * 32, by = blockIdx.y * 32;
    const int tx = threadIdx.x, ty = threadIdx.y;
#pragma unroll
    for (int r = 0; r < 32; r += 8)
        t[ty + r][tx] = Wm[(size_t)(by + ty + r) * C_ + bx + tx];
    __syncthreads();
#pragma unroll
    for (int r = 0; r < 32; r += 8)
        T[(size_t)(bx + ty + r) * C_ + by + tx] = t[tx][ty + r];
}

// ---------------------------------------------------------------------------
// Kernel 1: 1x1 conv GEMM (FFMA2, 128x128 tile, double-buffered) with fused
// GroupNorm partial-stats epilogue (smem reduce -> global atomicAdd).
// ---------------------------------------------------------------------------
__global__ __launch_bounds__(256, 2) void conv1x1_kernel(
    const float* __restrict__ X, int which)
{
    __shared__ __align__(16) float xs[2][16][128];
    __shared__ __align__(16) float ws[2][16][128];
    __shared__ float sg[16][2];                   // per-CTA group partials

    float* __restrict__ Y = which ? g_Yk : g_Yq;
    const float* __restrict__ Wt = g_Wt[which];

    const int tid = threadIdx.x;
    const int tx = tid & 15;
    const int ty = tid >> 4;
    const int s0 = blockIdx.x * 128;
    const int o0 = blockIdx.y * 128;
    const int b  = blockIdx.z;
    const float* Xb = X + (size_t)b * C_ * HW_;

    u64 acc[8][4];
#pragma unroll
    for (int m = 0; m < 8; m++)
#pragma unroll
        for (int u = 0; u < 4; u++) acc[m][u] = 0ull;

    const int lr = ty, lc = tx;

    float4 xg0, xg1, wg0, wg1;
    {
        const float* xp = Xb + (size_t)lr * HW_ + s0;
        xg0 = *(const float4*)(xp + lc * 4);
        xg1 = *(const float4*)(xp + 64 + lc * 4);
        const float* wp = Wt + (size_t)lr * C_ + o0;
        wg0 = *(const float4*)(wp + lc * 4);
        wg1 = *(const float4*)(wp + 64 + lc * 4);
    }
    *(float4*)&xs[0][lr][lc * 4]      = xg0;
    *(float4*)&xs[0][lr][64 + lc * 4] = xg1;
    *(float4*)&ws[0][lr][lc * 4]      = wg0;
    *(float4*)&ws[0][lr][64 + lc * 4] = wg1;
    if (tid < 32) ((float*)sg)[tid] = 0.f;
    __syncthreads();

    for (int ch = 0; ch < 16; ch++) {
        const int buf = ch & 1;
        if (ch < 15) {
            const int c0 = (ch + 1) * 16;
            const float* xp = Xb + (size_t)(c0 + lr) * HW_ + s0;
            xg0 = *(const float4*)(xp + lc * 4);
            xg1 = *(const float4*)(xp + 64 + lc * 4);
            const float* wp = Wt + (size_t)(c0 + lr) * C_ + o0;
            wg0 = *(const float4*)(wp + lc * 4);
            wg1 = *(const float4*)(wp + 64 + lc * 4);
        }
#pragma unroll
        for (int k = 0; k < 16; k++) {
            ulonglong2 xa = *(const ulonglong2*)&xs[buf][k][4 * tx];
            ulonglong2 xb = *(const ulonglong2*)&xs[buf][k][64 + 4 * tx];
            float4 wa = *(const float4*)&ws[buf][k][4 * ty];
            float4 wb = *(const float4*)&ws[buf][k][64 + 4 * ty];
            u64 wp2[8];
            wp2[0] = bcast2(wa.x); wp2[1] = bcast2(wa.y);
            wp2[2] = bcast2(wa.z); wp2[3] = bcast2(wa.w);
            wp2[4] = bcast2(wb.x); wp2[5] = bcast2(wb.y);
            wp2[6] = bcast2(wb.z); wp2[7] = bcast2(wb.w);
#pragma unroll
            for (int m = 0; m < 8; m++) {
                FMA2(acc[m][0], wp2[m], xa.x);
                FMA2(acc[m][1], wp2[m], xa.y);
                FMA2(acc[m][2], wp2[m], xb.x);
                FMA2(acc[m][3], wp2[m], xb.y);
            }
        }
        if (ch < 15) {
            const int nb = buf ^ 1;
            *(float4*)&xs[nb][lr][lc * 4]      = xg0;
            *(float4*)&xs[nb][lr][64 + lc * 4] = xg1;
            *(float4*)&ws[nb][lr][lc * 4]      = wg0;
            *(float4*)&ws[nb][lr][64 + lc * 4] = wg1;
            __syncthreads();
        }
    }

    // epilogue: store Y + accumulate GN partial stats
    float* Yb = Y + ((size_t)b * C_ + o0) * HW_ + s0;
#pragma unroll
    for (int m = 0; m < 8; m++) {
        const int ol = (m < 4) ? (4 * ty + m) : (64 + 4 * ty + (m - 4));
        float2 p0 = unpack2(acc[m][0]), p1 = unpack2(acc[m][1]);
        float2 p2 = unpack2(acc[m][2]), p3 = unpack2(acc[m][3]);
        *(float4*)(Yb + (size_t)ol * HW_ + 4 * tx)      = make_float4(p0.x, p0.y, p1.x, p1.y);
        *(float4*)(Yb + (size_t)ol * HW_ + 64 + 4 * tx) = make_float4(p2.x, p2.y, p3.x, p3.y);
        float s  = p0.x + p0.y + p1.x + p1.y + p2.x + p2.y + p3.x + p3.y;
        float ss = p0.x*p0.x + p0.y*p0.y + p1.x*p1.x + p1.y*p1.y
                 + p2.x*p2.x + p2.y*p2.y + p3.x*p3.x + p3.y*p3.y;
        atomicAdd(&sg[ol >> 3][0], s);
        atomicAdd(&sg[ol >> 3][1], ss);
    }
    __syncthreads();
    if (tid < 32)
        atomicAdd(&g_psum[which][b][(o0 >> 3) + (tid >> 1)][tid & 1], sg[tid >> 1][tid & 1]);
}

// ---------------------------------------------------------------------------
// Kernel 2: finalize GN stats (512 entries)
// ---------------------------------------------------------------------------
__global__ void gn_finalize() {
    const int t = threadIdx.x;                // 512
    const int te = t >> 8, b = (t >> 5) & 7, g = t & 31;
    const float inv = 1.0f / (float)(CPG_ * HW_);
    float s  = g_psum[te][b][g][0];
    float ss = g_psum[te][b][g][1];
    float mu  = s * inv;
    float var = ss * inv - mu * mu;
    g_stats[te][b][g] = make_float2(mu, rsqrtf(fmaxf(var, 0.f) + EPS_));
}

// ---------------------------------------------------------------------------
// Kernel 3: per-patch attention v3 — 2 CTAs/SM.
//   smem: ks[256][68] resident + bufQ[2][32][68] streamed + A[64][68]
//   = 104448 B  ->  occupancy 2 hides all phase latencies across CTAs.
// ---------------------------------------------------------------------------
#define ATTN_SMEM ((256 * AST + 2 * 32 * AST + 64 * AST) * 4)   // 104448

__global__ __launch_bounds__(256, 2) void attn_kernel(
    const float* __restrict__ xlow,
    const float* __restrict__ gq, const float* __restrict__ bq,
    const float* __restrict__ gk, const float* __restrict__ bk,
    float* __restrict__ out)
{
    extern __shared__ __align__(16) float sm[];
    float* ks   = sm;                          // [256][AST]
    float* bufQ = sm + 256 * AST;              // [2][32][AST]
    float* A    = sm + (256 + 64) * AST;       // [64][AST]

    const int n  = blockIdx.x;
    const int b  = n >> 8;
    const int ph = (n >> 4) & 15;
    const int pw = n & 15;
    const int tid = threadIdx.x;
    const size_t pbase = (size_t)b * C_ * HW_ + (size_t)(ph * 8) * W_ + pw * 8;

    const int cl = tid >> 3, il = tid & 7;     // loader coords: c-row, patch row
    const size_t lbase = pbase + (size_t)il * W_;

    // --- load + normalize full k (resident) ---
#pragma unroll
    for (int pass = 0; pass < 8; pass++) {
        const int c = pass * 32 + cl;
        const float2 st = g_stats[1][b][c >> 3];
        const float ak = st.y * __ldg(gk + c), ck = __ldg(bk + c) - st.x * ak;
        const float* src = g_Yk + lbase + (size_t)c * HW_;
        float4 v0 = *(const float4*)src;
        float4 v1 = *(const float4*)(src + 4);
        *(float4*)&ks[c * AST + il * 8]     = make_float4(v0.x*ak+ck, v0.y*ak+ck, v0.z*ak+ck, v0.w*ak+ck);
        *(float4*)&ks[c * AST + il * 8 + 4] = make_float4(v1.x*ak+ck, v1.y*ak+ck, v1.z*ak+ck, v1.w*ak+ck);
    }

    // --- q chunk 0 ---
    float4 q0, q1; float aq, cq;
    {
        const int c = cl;
        const float2 st = g_stats[0][b][c >> 3];
        aq = st.y * __ldg(gq + c); cq = __ldg(bq + c) - st.x * aq;
        const float* src = g_Yq + lbase + (size_t)c * HW_;
        q0 = *(const float4*)src; q1 = *(const float4*)(src + 4);
    }
    *(float4*)&bufQ[cl * AST + il * 8]     = make_float4(q0.x*aq+cq, q0.y*aq+cq, q0.z*aq+cq, q0.w*aq+cq);
    *(float4*)&bufQ[cl * AST + il * 8 + 4] = make_float4(q1.x*aq+cq, q1.y*aq+cq, q1.z*aq+cq, q1.w*aq+cq);
    __syncthreads();

    // --- S = q^T k : 4x4 tile per thread, q streamed in 8 chunks ---
    const int tx = tid & 15, ty = tid >> 4;    // cols 4tx.., rows 4ty..
    u64 sacc[4][2];
#pragma unroll
    for (int m = 0; m < 4; m++) { sacc[m][0] = 0ull; sacc[m][1] = 0ull; }

    for (int ch = 0; ch < 8; ch++) {
        const int buf = ch & 1;
        if (ch < 7) {
            const int c = (ch + 1) * 32 + cl;
            const float2 st = g_stats[0][b][c >> 3];
            aq = st.y * __ldg(gq + c); cq = __ldg(bq + c) - st.x * aq;
            const float* src = g_Yq + lbase + (size_t)c * HW_;
            q0 = *(const float4*)src; q1 = *(const float4*)(src + 4);
        }
        const float* bq_ = bufQ + buf * 32 * AST + 4 * ty;
        const float* ks_ = ks + (ch * 32) * AST + 4 * tx;
#pragma unroll 4
        for (int cc = 0; cc < 32; cc++) {
            float4 qv = *(const float4*)(bq_ + cc * AST);
            ulonglong2 kv = *(const ulonglong2*)(ks_ + cc * AST);
            u64 qp0 = bcast2(qv.x), qp1 = bcast2(qv.y), qp2 = bcast2(qv.z), qp3 = bcast2(qv.w);
            FMA2(sacc[0][0], qp0, kv.x); FMA2(sacc[0][1], qp0, kv.y);
            FMA2(sacc[1][0], qp1, kv.x); FMA2(sacc[1][1], qp1, kv.y);
            FMA2(sacc[2][0], qp2, kv.x); FMA2(sacc[2][1], qp2, kv.y);
            FMA2(sacc[3][0], qp3, kv.x); FMA2(sacc[3][1], qp3, kv.y);
        }
        if (ch < 7) {
            __syncthreads();
            const int nb = buf ^ 1;
            *(float4*)&bufQ[nb * 32 * AST + cl * AST + il * 8]     = make_float4(q0.x*aq+cq, q0.y*aq+cq, q0.z*aq+cq, q0.w*aq+cq);
            *(float4*)&bufQ[nb * 32 * AST + cl * AST + il * 8 + 4] = make_float4(q1.x*aq+cq, q1.y*aq+cq, q1.z*aq+cq, q1.w*aq+cq);
            __syncthreads();
        }
    }
#pragma unroll
    for (int m = 0; m < 4; m++)
        *(ulonglong2*)&A[(4 * ty + m) * AST + 4 * tx] = make_ulonglong2(sacc[m][0], sacc[m][1]);
    __syncthreads();

    // --- softmax: 4 lanes per row (rows = tid>>2, segment = tid&3) ---
    {
        float* row = A + (tid >> 2) * AST + (tid & 3) * 16;
        float mx = -1e30f;
#pragma unroll
        for (int j = 0; j < 16; j++) mx = fmaxf(mx, row[j] * 0.0625f);
        mx = fmaxf(mx, __shfl_xor_sync(0xffffffffu, mx, 1));
        mx = fmaxf(mx, __shfl_xor_sync(0xffffffffu, mx, 2));
        float s = 0.f;
#pragma unroll
        for (int j = 0; j < 16; j++) { float e = __expf(row[j] * 0.0625f - mx); row[j] = e; s += e; }
        s += __shfl_xor_sync(0xffffffffu, s, 1);
        s += __shfl_xor_sync(0xffffffffu, s, 2);
        const float inv = 1.0f / s;
#pragma unroll
        for (int j = 0; j < 16; j++) row[j] *= inv;
    }
    __syncthreads();

    // --- O = A k^T in two c-halves, direct global writeback with residual ---
    const int pg = tid & 7, cg = tid >> 3;     // p rows pg+8jp ; c cols h*128+cg+32jc
#pragma unroll 1
    for (int h = 0; h < 2; h++) {
        u64 oacc[8][4];
#pragma unroll
        for (int jp = 0; jp < 8; jp++)
#pragma unroll
            for (int jc = 0; jc < 4; jc++) oacc[jp][jc] = 0ull;

        const float* kb = ks + (h * 128 + cg) * AST;
#pragma unroll 4
        for (int ppb = 0; ppb < 16; ppb++) {
            ulonglong2 ap[8];
#pragma unroll
            for (int jp = 0; jp < 8; jp++)
                ap[jp] = *(const ulonglong2*)&A[(pg + 8 * jp) * AST + 4 * ppb];
#pragma unroll
            for (int jc = 0; jc < 4; jc++) {
                ulonglong2 kp = *(const ulonglong2*)(kb + jc * 32 * AST + 4 * ppb);
#pragma unroll
                for (int jp = 0; jp < 8; jp++) {
                    FMA2(oacc[jp][jc], ap[jp].x, kp.x);
                    FMA2(oacc[jp][jc], ap[jp].y, kp.y);
                }
            }
        }
#pragma unroll
        for (int jc = 0; jc < 4; jc++) {
            const int c = h * 128 + cg + 32 * jc;
            const size_t cb = pbase + (size_t)c * HW_ + pg;
#pragma unroll
            for (int jp = 0; jp < 8; jp++) {
                float2 v = unpack2(oacc[jp][jc]);
                const size_t off = cb + (size_t)jp * W_;
                out[off] = v.x + v.y + __ldg(xlow + off);
            }
        }
    }
}

// ---------------------------------------------------------------------------
// Launch
// ---------------------------------------------------------------------------
extern "C" void kernel_launch(void* const* d_in, const int* in_sizes, int n_in,
                              void* d_out, int out_size)
{
    const float* x_low  = (const float*)d_in[0];
    const float* x_high = (const float*)d_in[1];
    const float* Wq     = (const float*)d_in[2];
    const float* gq     = (const float*)d_in[3];
    const float* bq     = (const float*)d_in[4];
    const float* Wk     = (const float*)d_in[5];
    const float* gk     = (const float*)d_in[6];
    const float* bk     = (const float*)d_in[7];
    float* out = (float*)d_out;

    cudaFuncSetAttribute(attn_kernel, cudaFuncAttributeMaxDynamicSharedMemorySize, ATTN_SMEM);

    init_kernel<<<1, 1024>>>();
    wtrans_kernel<<<dim3(8, 8, 2), dim3(32, 8)>>>(Wq, Wk);

    dim3 cgrid(HW_ / 128, C_ / 128, B_);
    conv1x1_kernel<<<cgrid, 256>>>(x_low,  0);
    conv1x1_kernel<<<cgrid, 256>>>(x_high, 1);
    gn_finalize<<<1, 512>>>();
    attn_kernel<<<2048, 256, ATTN_SMEM>>>(x_low, gq, bq, gk, bk, out);
}